// round 2
// baseline (speedup 1.0000x reference)
#include <cuda_runtime.h>

// Problem dims
#define BSZ   512     // batch
#define HID   512     // hidden
#define GATES 2048    // 4*HID
#define TSEQ  128     // encoder timesteps
#define HOR   24      // decoder horizon
#define INDIM 2

// Tiling
#define BM    128     // batch rows per CTA
#define TH    16      // hidden cols per CTA (x4 quadrants = 64 gate cols)
#define BK    16      // k-tile
#define NTHR  256

#define BH (BSZ*HID)

// ---------------- device scratch (static: no allocations allowed) ----------
__device__ float g_hs1[TSEQ*BH];      // encoder layer-1 outputs (also its h chain)
__device__ float g_h1a[BH];
__device__ float g_h1b[BH];
__device__ float g_h2a[BH];
__device__ float g_h2b[BH];
__device__ float g_c1[BH];
__device__ float g_c2[BH];
__device__ float g_zero[BH];
__device__ float g_decin[BSZ*INDIM];

struct SmemT {
    float As[BK][BM + 4];     // k-major A tile, padded for float4-friendly banks
    float Ws[64][BK + 1];     // 4 quadrants x 16 hidden cols, padded
};

__device__ __forceinline__ float fast_sigmoid(float x) {
    return 1.0f / (1.0f + __expf(-x));
}
__device__ __forceinline__ float fast_tanh(float x) {
    // exact-enough tanh via exp: 1 - 2/(e^{2x}+1); saturates correctly at +-inf
    return 1.0f - 2.0f / (__expf(2.0f * x) + 1.0f);
}

// Accumulate acc[jb][q] += sum_k A[b, k] * W[q*HID + hc, k]  over K=HID.
// A row stride = HID, W row stride = HID (all big operands are [., 512]).
__device__ __forceinline__ void gemm_half(
    const float* __restrict__ A,
    const float* __restrict__ W,
    int b0, int hc0, int tx, int ty, int tid,
    float acc[8][4], SmemT& s)
{
    for (int k0 = 0; k0 < HID; k0 += BK) {
        __syncthreads();
        // Load A tile: BM x BK (coalesced 64B segments along k)
        #pragma unroll
        for (int i = 0; i < (BM * BK) / NTHR; i++) {
            int idx = tid + i * NTHR;
            int r = idx >> 4, c = idx & 15;
            s.As[c][r] = A[(b0 + r) * HID + k0 + c];
        }
        // Load W tile: 64 rows (4 quadrants x TH) x BK
        #pragma unroll
        for (int i = 0; i < (64 * BK) / NTHR; i++) {
            int idx = tid + i * NTHR;
            int row = idx >> 4, c = idx & 15;
            int q = row >> 4, hcd = row & 15;
            s.Ws[row][c] = W[(q * HID + hc0 + hcd) * HID + k0 + c];
        }
        __syncthreads();
        #pragma unroll
        for (int k = 0; k < BK; k++) {
            float4 a0 = *reinterpret_cast<const float4*>(&s.As[k][ty * 8]);
            float4 a1 = *reinterpret_cast<const float4*>(&s.As[k][ty * 8 + 4]);
            float w0 = s.Ws[tx][k];
            float w1 = s.Ws[16 + tx][k];
            float w2 = s.Ws[32 + tx][k];
            float w3 = s.Ws[48 + tx][k];
            float av[8] = {a0.x, a0.y, a0.z, a0.w, a1.x, a1.y, a1.z, a1.w};
            #pragma unroll
            for (int jb = 0; jb < 8; jb++) {
                acc[jb][0] += av[jb] * w0;
                acc[jb][1] += av[jb] * w1;
                acc[jb][2] += av[jb] * w2;
                acc[jb][3] += av[jb] * w3;
            }
        }
    }
}

// One LSTM cell step, fully fused:
//   gates = A1 @ W1^T  (K1==HID via GEMM, K1==2 via scalar epilogue)
//         + Hin @ Whh^T + bih + bhh
//   then i,f,g,o -> c,h update. Hout/C written per-element by the owning thread.
__global__ void __launch_bounds__(NTHR)
lstm_step(const float* __restrict__ A1, int lda1,
          const float* __restrict__ W1, int K1,
          const float* __restrict__ Hin, const float* __restrict__ Whh,
          const float* __restrict__ bih, const float* __restrict__ bhh,
          float* __restrict__ Hout, float* __restrict__ C)
{
    __shared__ SmemT s;
    int tid = threadIdx.x;
    int tx = tid & 15;        // hidden col within tile
    int ty = tid >> 4;        // batch group (8 rows each)
    int hc0 = blockIdx.x * TH;
    int b0  = blockIdx.y * BM;

    float acc[8][4];
    #pragma unroll
    for (int jb = 0; jb < 8; jb++)
        #pragma unroll
        for (int q = 0; q < 4; q++) acc[jb][q] = 0.0f;

    if (K1 == HID) gemm_half(A1, W1, b0, hc0, tx, ty, tid, acc, s);
    gemm_half(Hin, Whh, b0, hc0, tx, ty, tid, acc, s);

    // Epilogue
    int hc = hc0 + tx;
    float bsum[4], wk0[4], wk1[4];
    #pragma unroll
    for (int q = 0; q < 4; q++) {
        int g = q * HID + hc;
        bsum[q] = bih[g] + bhh[g];
        if (K1 == INDIM) { wk0[q] = W1[g * INDIM + 0]; wk1[q] = W1[g * INDIM + 1]; }
    }
    #pragma unroll
    for (int jb = 0; jb < 8; jb++) {
        int b = b0 + ty * 8 + jb;
        float gv[4];
        #pragma unroll
        for (int q = 0; q < 4; q++) gv[q] = acc[jb][q] + bsum[q];
        if (K1 == INDIM) {
            float xi0 = A1[b * lda1 + 0];
            float xi1 = A1[b * lda1 + 1];
            #pragma unroll
            for (int q = 0; q < 4; q++) gv[q] += xi0 * wk0[q] + xi1 * wk1[q];
        }
        float ig = fast_sigmoid(gv[0]);
        float fg = fast_sigmoid(gv[1]);
        float gg = fast_tanh(gv[2]);
        float og = fast_sigmoid(gv[3]);
        int idx = b * HID + hc;
        float c = C[idx];
        c = fg * c + ig * gg;
        C[idx] = c;
        Hout[idx] = og * fast_tanh(c);
    }
}

// pred[b,k] = h2[b,:] . fcW[k,:] + fcb[k]; writes to out[b, s, k] and g_decin
__global__ void pred_kernel(const float* __restrict__ h2,
                            const float* __restrict__ fcW,
                            const float* __restrict__ fcb,
                            float* __restrict__ out, int s)
{
    int warp = threadIdx.x >> 5;
    int lane = threadIdx.x & 31;
    int b = blockIdx.x * 4 + warp;
    const float* hrow = h2 + b * HID;
    float a0 = 0.0f, a1 = 0.0f;
    #pragma unroll
    for (int j = lane; j < HID; j += 32) {
        float h = hrow[j];
        a0 += h * fcW[j];
        a1 += h * fcW[HID + j];
    }
    #pragma unroll
    for (int o = 16; o; o >>= 1) {
        a0 += __shfl_xor_sync(0xffffffffu, a0, o);
        a1 += __shfl_xor_sync(0xffffffffu, a1, o);
    }
    if (lane == 0) {
        float p0 = a0 + fcb[0], p1 = a1 + fcb[1];
        out[b * HOR * 2 + s * 2 + 0] = p0;
        out[b * HOR * 2 + s * 2 + 1] = p1;
        g_decin[b * 2 + 0] = p0;
        g_decin[b * 2 + 1] = p1;
    }
}

__global__ void zero_init() {
    int i = blockIdx.x * blockDim.x + threadIdx.x;
    if (i < BH) {
        g_zero[i] = 0.0f;
        g_c1[i] = 0.0f;
        g_c2[i] = 0.0f;
    }
    if (i < BSZ * INDIM) g_decin[i] = 0.0f;
}

extern "C" void kernel_launch(void* const* d_in, const int* in_sizes, int n_in,
                              void* d_out, int out_size)
{
    const float* x      = (const float*)d_in[0];
    const float* eWih0  = (const float*)d_in[1];
    const float* eWhh0  = (const float*)d_in[2];
    const float* ebih0  = (const float*)d_in[3];
    const float* ebhh0  = (const float*)d_in[4];
    const float* eWih1  = (const float*)d_in[5];
    const float* eWhh1  = (const float*)d_in[6];
    const float* ebih1  = (const float*)d_in[7];
    const float* ebhh1  = (const float*)d_in[8];
    const float* dWih0  = (const float*)d_in[9];
    const float* dWhh0  = (const float*)d_in[10];
    const float* dbih0  = (const float*)d_in[11];
    const float* dbhh0  = (const float*)d_in[12];
    const float* dWih1  = (const float*)d_in[13];
    const float* dWhh1  = (const float*)d_in[14];
    const float* dbih1  = (const float*)d_in[15];
    const float* dbhh1  = (const float*)d_in[16];
    const float* fcW    = (const float*)d_in[17];
    const float* fcb    = (const float*)d_in[18];
    float* out = (float*)d_out;

    float *hs1, *h1a, *h1b, *h2a, *h2b, *c1, *c2, *zero, *decin;
    cudaGetSymbolAddress((void**)&hs1,   g_hs1);
    cudaGetSymbolAddress((void**)&h1a,   g_h1a);
    cudaGetSymbolAddress((void**)&h1b,   g_h1b);
    cudaGetSymbolAddress((void**)&h2a,   g_h2a);
    cudaGetSymbolAddress((void**)&h2b,   g_h2b);
    cudaGetSymbolAddress((void**)&c1,    g_c1);
    cudaGetSymbolAddress((void**)&c2,    g_c2);
    cudaGetSymbolAddress((void**)&zero,  g_zero);
    cudaGetSymbolAddress((void**)&decin, g_decin);

    zero_init<<<(BH + 255) / 256, 256>>>();

    dim3 grid(HID / TH, BSZ / BM);   // (32, 4) = 128 CTAs

    // Encoder layer 1: h chain lives in g_hs1 (outputs ARE the chain)
    for (int t = 0; t < TSEQ; t++) {
        const float* hin = t ? (hs1 + (size_t)(t - 1) * BH) : zero;
        lstm_step<<<grid, NTHR>>>(x + t * INDIM, TSEQ * INDIM, eWih0, INDIM,
                                  hin, eWhh0, ebih0, ebhh0,
                                  hs1 + (size_t)t * BH, c1);
    }
    // Encoder layer 2: ping-pong h2a/h2b; final state ends in h2b (T even)
    for (int t = 0; t < TSEQ; t++) {
        const float* hin = (t == 0) ? zero : ((t & 1) ? h2a : h2b);
        float* hout = (t & 1) ? h2b : h2a;
        lstm_step<<<grid, NTHR>>>(hs1 + (size_t)t * BH, HID, eWih1, HID,
                                  hin, eWhh1, ebih1, ebhh1, hout, c2);
    }
    // Decoder: initial states = encoder finals (h1: hs1[T-1], c1; h2: h2b, c2)
    for (int s = 0; s < HOR; s++) {
        const float* h1in = (s == 0) ? (hs1 + (size_t)(TSEQ - 1) * BH)
                                     : ((s & 1) ? h1a : h1b);
        float* h1out = (s & 1) ? h1b : h1a;
        lstm_step<<<grid, NTHR>>>(decin, INDIM, dWih0, INDIM,
                                  h1in, dWhh0, dbih0, dbhh0, h1out, c1);

        const float* h2in = (s == 0) ? h2b : ((s & 1) ? h2a : h2b);
        float* h2out = (s & 1) ? h2b : h2a;
        lstm_step<<<grid, NTHR>>>(h1out, HID, dWih1, HID,
                                  h2in, dWhh1, dbih1, dbhh1, h2out, c2);

        pred_kernel<<<BSZ / 4, 128>>>(h2out, fcW, fcb, out, s);
    }
}

// round 4
// speedup vs baseline: 2.1877x; 2.1877x over previous
#include <cuda_runtime.h>
#include <cuda_bf16.h>

// Problem dims
#define BSZ   512
#define HID   512
#define TSEQ  128
#define HOR   24
#define INDIM 2

// Tiling
#define BM    128     // batch rows per CTA
#define TH    16      // hidden cols per CTA (x4 quadrants = 64 gate cols)
#define BN    64
#define BK    32
#define NTHR  256
#define BH (BSZ*HID)
#define SROW  (BK+8)  // padded smem row (40 elems = 80B, 16B-aligned, conflict-free ldmatrix)

// ---------------- device scratch (static; packed bf16 (hi|lo<<16) pairs) ----
__device__ unsigned g_hs1[TSEQ*BH];   // encoder layer-1 outputs / recurrent chain
__device__ unsigned g_h1a[BH];
__device__ unsigned g_h1b[BH];
__device__ unsigned g_h2a[BH];
__device__ unsigned g_h2b[BH];
__device__ unsigned g_zero[BH];
__device__ float    g_c1[BH];
__device__ float    g_c2[BH];
__device__ float    g_decin[BSZ*INDIM];
// split weights: 0=eWhh0 1=eWih1 2=eWhh1 3=dWhh0 4=dWih1 5=dWhh1
__device__ unsigned g_w[6][4*HID*HID];

struct GSmem {
    __nv_bfloat16 Ah[BM][SROW];
    __nv_bfloat16 Al[BM][SROW];
    __nv_bfloat16 Bh[BN][SROW];
    __nv_bfloat16 Bl[BN][SROW];
};
union __align__(16) USmem {
    GSmem g;
    float gm[BM][BN + 4];   // gate values for the fused cell-update epilogue
};

__device__ __forceinline__ float fast_sigmoid(float x) {
    return 1.0f / (1.0f + __expf(-x));
}
__device__ __forceinline__ float fast_tanh(float x) {
    return 1.0f - 2.0f / (__expf(2.0f * x) + 1.0f);
}

__device__ __forceinline__ void mma_bf16(float* c, const unsigned* a, const unsigned* b) {
    asm volatile(
        "mma.sync.aligned.m16n8k16.row.col.f32.bf16.bf16.f32 "
        "{%0,%1,%2,%3}, {%4,%5,%6,%7}, {%8,%9}, {%0,%1,%2,%3};\n"
        : "+f"(c[0]), "+f"(c[1]), "+f"(c[2]), "+f"(c[3])
        : "r"(a[0]), "r"(a[1]), "r"(a[2]), "r"(a[3]), "r"(b[0]), "r"(b[1]));
}

__device__ __forceinline__ void ldsm4(unsigned* r, const void* p) {
    unsigned addr = (unsigned)__cvta_generic_to_shared(p);
    asm volatile("ldmatrix.sync.aligned.m8n8.x4.shared.b16 {%0,%1,%2,%3}, [%4];"
        : "=r"(r[0]), "=r"(r[1]), "=r"(r[2]), "=r"(r[3]) : "r"(addr));
}

// Accumulate acc += A[b0+.., :] @ W[gate, :]^T over K=HID with 3-pass bf16 split.
// A: [*,512] packed pairs (row = batch). W: [2048,512] packed pairs.
__device__ __forceinline__ void gemm_half(
    const unsigned* __restrict__ A,
    const unsigned* __restrict__ W,
    int b0, int hc0, float acc[2][4][4], USmem& s)
{
    const int tid = threadIdx.x;
    const int wid = tid >> 5, lane = tid & 31;
    const int wm = wid >> 1, wn = wid & 1;
    // ldmatrix lane addressing
    const int a_row = (lane & 7) + ((lane >> 3) & 1) * 8;  // + wm*32 + mt*16
    const int a_col = (lane >> 4) * 8;                     // + kk*16
    const int b_row = (lane >> 4) * 8 + (lane & 7);        // + wn*32 + p*16
    const int b_col = ((lane >> 3) & 1) * 8;               // + kk*16

    for (int k0 = 0; k0 < HID; k0 += BK) {
        __syncthreads();
        // stage A: 128 x 32 packed u32, split hi/lo into bf16 tiles
        #pragma unroll
        for (int i = 0; i < 4; i++) {
            int idx = tid + i * NTHR;            // 0..1023 over 128x8 uint4
            int r = idx >> 3, c4 = (idx & 7) * 4;
            uint4 v = *reinterpret_cast<const uint4*>(&A[(b0 + r) * HID + k0 + c4]);
            unsigned hA = (v.x & 0xffffu) | (v.y << 16);
            unsigned hB = (v.z & 0xffffu) | (v.w << 16);
            unsigned lA = (v.x >> 16) | (v.y & 0xffff0000u);
            unsigned lB = (v.z >> 16) | (v.w & 0xffff0000u);
            *reinterpret_cast<uint2*>(&s.g.Ah[r][c4]) = make_uint2(hA, hB);
            *reinterpret_cast<uint2*>(&s.g.Al[r][c4]) = make_uint2(lA, lB);
        }
        // stage B: 64 x 32 (rows = q*16+hcd -> gate q*512+hc0+hcd)
        #pragma unroll
        for (int i = 0; i < 2; i++) {
            int idx = tid + i * NTHR;            // 0..511 over 64x8 uint4
            int r = idx >> 3, c4 = (idx & 7) * 4;
            int gg = (r >> 4) * HID + hc0 + (r & 15);
            uint4 v = *reinterpret_cast<const uint4*>(&W[gg * HID + k0 + c4]);
            unsigned hA = (v.x & 0xffffu) | (v.y << 16);
            unsigned hB = (v.z & 0xffffu) | (v.w << 16);
            unsigned lA = (v.x >> 16) | (v.y & 0xffff0000u);
            unsigned lB = (v.z >> 16) | (v.w & 0xffff0000u);
            *reinterpret_cast<uint2*>(&s.g.Bh[r][c4]) = make_uint2(hA, hB);
            *reinterpret_cast<uint2*>(&s.g.Bl[r][c4]) = make_uint2(lA, lB);
        }
        __syncthreads();
        #pragma unroll
        for (int kk = 0; kk < 2; kk++) {
            unsigned ah[2][4], al[2][4], bh[2][4], bl[2][4];
            #pragma unroll
            for (int mt = 0; mt < 2; mt++) {
                ldsm4(ah[mt], &s.g.Ah[wm * 32 + mt * 16 + a_row][kk * 16 + a_col]);
                ldsm4(al[mt], &s.g.Al[wm * 32 + mt * 16 + a_row][kk * 16 + a_col]);
            }
            #pragma unroll
            for (int p = 0; p < 2; p++) {
                ldsm4(bh[p], &s.g.Bh[wn * 32 + p * 16 + b_row][kk * 16 + b_col]);
                ldsm4(bl[p], &s.g.Bl[wn * 32 + p * 16 + b_row][kk * 16 + b_col]);
            }
            #pragma unroll
            for (int mt = 0; mt < 2; mt++)
                #pragma unroll
                for (int nb = 0; nb < 4; nb++) {
                    const unsigned* B2h = &bh[nb >> 1][(nb & 1) * 2];
                    const unsigned* B2l = &bl[nb >> 1][(nb & 1) * 2];
                    mma_bf16(acc[mt][nb], ah[mt], B2h);
                    mma_bf16(acc[mt][nb], ah[mt], B2l);
                    mma_bf16(acc[mt][nb], al[mt], B2h);
                }
        }
    }
}

// One fused LSTM step.
// mode 0: input projection is K=2 scalar epilogue (x1 fp32, Wx fp32 [2048,2]).
// mode 1: input projection is a full K=512 GEMM (A1u, W1u packed pairs).
__global__ void __launch_bounds__(NTHR, 1)
lstm_step(const unsigned* __restrict__ A1u, const unsigned* __restrict__ W1u,
          const float* __restrict__ x1, int lda1, const float* __restrict__ Wx,
          const unsigned* __restrict__ Hin, const unsigned* __restrict__ Whh,
          const float* __restrict__ bih, const float* __restrict__ bhh,
          unsigned* __restrict__ Hout, float* __restrict__ C, int mode)
{
    __shared__ USmem s;
    const int tid = threadIdx.x;
    const int wid = tid >> 5, lane = tid & 31;
    const int wm = wid >> 1, wn = wid & 1;
    const int hc0 = blockIdx.x * TH;
    const int b0  = blockIdx.y * BM;

    float acc[2][4][4];
    #pragma unroll
    for (int mt = 0; mt < 2; mt++)
        #pragma unroll
        for (int nb = 0; nb < 4; nb++)
            #pragma unroll
            for (int r = 0; r < 4; r++) acc[mt][nb][r] = 0.0f;

    if (mode == 1) gemm_half(A1u, W1u, b0, hc0, acc, s);
    gemm_half(Hin, Whh, b0, hc0, acc, s);

    // ---- epilogue: gate transpose through smem, then fused cell update ----
    __syncthreads();
    {
        int g = lane >> 2, t = lane & 3;
        #pragma unroll
        for (int mt = 0; mt < 2; mt++)
            #pragma unroll
            for (int nb = 0; nb < 4; nb++) {
                int row = wm * 32 + mt * 16 + g;
                int col = wn * 32 + nb * 8 + t * 2;
                s.gm[row][col]         = acc[mt][nb][0];
                s.gm[row][col + 1]     = acc[mt][nb][1];
                s.gm[row + 8][col]     = acc[mt][nb][2];
                s.gm[row + 8][col + 1] = acc[mt][nb][3];
            }
    }
    __syncthreads();
    #pragma unroll
    for (int i = 0; i < 8; i++) {
        int idx = tid + i * NTHR;      // 0..2047 over 128 batch x 16 hc
        int hcd = idx & 15, br = idx >> 4;
        int b = b0 + br, hc = hc0 + hcd;
        float gv[4];
        #pragma unroll
        for (int q = 0; q < 4; q++)
            gv[q] = s.gm[br][q * 16 + hcd] + bih[q * HID + hc] + bhh[q * HID + hc];
        if (mode == 0) {
            float xi0 = x1[b * lda1 + 0];
            float xi1 = x1[b * lda1 + 1];
            #pragma unroll
            for (int q = 0; q < 4; q++) {
                int gg = q * HID + hc;
                gv[q] += xi0 * Wx[gg * INDIM + 0] + xi1 * Wx[gg * INDIM + 1];
            }
        }
        float ig = fast_sigmoid(gv[0]);
        float fg = fast_sigmoid(gv[1]);
        float gg = fast_tanh(gv[2]);
        float og = fast_sigmoid(gv[3]);
        int ci = b * HID + hc;
        float c = C[ci];
        c = fg * c + ig * gg;
        C[ci] = c;
        float h = og * fast_tanh(c);
        __nv_bfloat16 hh = __float2bfloat16(h);
        float resid = h - __bfloat162float(hh);
        __nv_bfloat16 hl = __float2bfloat16(resid);
        Hout[ci] = (unsigned)__bfloat16_as_ushort(hh)
                 | ((unsigned)__bfloat16_as_ushort(hl) << 16);
    }
}

// Split fp32 weights into packed (hi, lo) bf16 pairs.
__global__ void convert_w(const float* __restrict__ src, unsigned* __restrict__ dst, int n) {
    int i = blockIdx.x * blockDim.x + threadIdx.x;
    if (i < n) {
        float w = src[i];
        __nv_bfloat16 h = __float2bfloat16(w);
        float r = w - __bfloat162float(h);
        __nv_bfloat16 l = __float2bfloat16(r);
        dst[i] = (unsigned)__bfloat16_as_ushort(h)
               | ((unsigned)__bfloat16_as_ushort(l) << 16);
    }
}

// pred[b,k] = (hi+lo)(h2[b,:]) . fcW[k,:] + fcb[k]
__global__ void pred_kernel(const unsigned* __restrict__ h2,
                            const float* __restrict__ fcW,
                            const float* __restrict__ fcb,
                            float* __restrict__ out, int s)
{
    int warp = threadIdx.x >> 5;
    int lane = threadIdx.x & 31;
    int b = blockIdx.x * 4 + warp;
    const unsigned* hrow = h2 + b * HID;
    float a0 = 0.0f, a1 = 0.0f;
    #pragma unroll
    for (int j = lane; j < HID; j += 32) {
        unsigned u = hrow[j];
        float h = __bfloat162float(__ushort_as_bfloat16((unsigned short)(u & 0xffffu)))
                + __bfloat162float(__ushort_as_bfloat16((unsigned short)(u >> 16)));
        a0 += h * fcW[j];
        a1 += h * fcW[HID + j];
    }
    #pragma unroll
    for (int o = 16; o; o >>= 1) {
        a0 += __shfl_xor_sync(0xffffffffu, a0, o);
        a1 += __shfl_xor_sync(0xffffffffu, a1, o);
    }
    if (lane == 0) {
        float p0 = a0 + fcb[0], p1 = a1 + fcb[1];
        out[b * HOR * 2 + s * 2 + 0] = p0;
        out[b * HOR * 2 + s * 2 + 1] = p1;
        g_decin[b * 2 + 0] = p0;
        g_decin[b * 2 + 1] = p1;
    }
}

__global__ void zero_init() {
    int i = blockIdx.x * blockDim.x + threadIdx.x;
    if (i < BH) {
        g_zero[i] = 0u;
        g_c1[i] = 0.0f;
        g_c2[i] = 0.0f;
    }
    if (i < BSZ * INDIM) g_decin[i] = 0.0f;
}

extern "C" void kernel_launch(void* const* d_in, const int* in_sizes, int n_in,
                              void* d_out, int out_size)
{
    const float* x      = (const float*)d_in[0];
    const float* eWih0  = (const float*)d_in[1];
    const float* eWhh0  = (const float*)d_in[2];
    const float* ebih0  = (const float*)d_in[3];
    const float* ebhh0  = (const float*)d_in[4];
    const float* eWih1  = (const float*)d_in[5];
    const float* eWhh1  = (const float*)d_in[6];
    const float* ebih1  = (const float*)d_in[7];
    const float* ebhh1  = (const float*)d_in[8];
    const float* dWih0  = (const float*)d_in[9];
    const float* dWhh0  = (const float*)d_in[10];
    const float* dbih0  = (const float*)d_in[11];
    const float* dbhh0  = (const float*)d_in[12];
    const float* dWih1  = (const float*)d_in[13];
    const float* dWhh1  = (const float*)d_in[14];
    const float* dbih1  = (const float*)d_in[15];
    const float* dbhh1  = (const float*)d_in[16];
    const float* fcW    = (const float*)d_in[17];
    const float* fcb    = (const float*)d_in[18];
    float* out = (float*)d_out;

    unsigned *hs1, *h1a, *h1b, *h2a, *h2b, *zero, *wbase;
    float *c1, *c2, *decin;
    cudaGetSymbolAddress((void**)&hs1,   g_hs1);
    cudaGetSymbolAddress((void**)&h1a,   g_h1a);
    cudaGetSymbolAddress((void**)&h1b,   g_h1b);
    cudaGetSymbolAddress((void**)&h2a,   g_h2a);
    cudaGetSymbolAddress((void**)&h2b,   g_h2b);
    cudaGetSymbolAddress((void**)&zero,  g_zero);
    cudaGetSymbolAddress((void**)&c1,    g_c1);
    cudaGetSymbolAddress((void**)&c2,    g_c2);
    cudaGetSymbolAddress((void**)&decin, g_decin);
    cudaGetSymbolAddress((void**)&wbase, g_w);
    const int WSZ = 4 * HID * HID;
    unsigned* w_eWhh0 = wbase + 0 * WSZ;
    unsigned* w_eWih1 = wbase + 1 * WSZ;
    unsigned* w_eWhh1 = wbase + 2 * WSZ;
    unsigned* w_dWhh0 = wbase + 3 * WSZ;
    unsigned* w_dWih1 = wbase + 4 * WSZ;
    unsigned* w_dWhh1 = wbase + 5 * WSZ;

    zero_init<<<(BH + 255) / 256, 256>>>();
    {
        int nb = (WSZ + 255) / 256;
        convert_w<<<nb, 256>>>(eWhh0, w_eWhh0, WSZ);
        convert_w<<<nb, 256>>>(eWih1, w_eWih1, WSZ);
        convert_w<<<nb, 256>>>(eWhh1, w_eWhh1, WSZ);
        convert_w<<<nb, 256>>>(dWhh0, w_dWhh0, WSZ);
        convert_w<<<nb, 256>>>(dWih1, w_dWih1, WSZ);
        convert_w<<<nb, 256>>>(dWhh1, w_dWhh1, WSZ);
    }

    dim3 grid(HID / TH, BSZ / BM);   // (32, 4) = 128 CTAs

    // Encoder layer 1 (mode 0: x epilogue). h chain lives in g_hs1.
    for (int t = 0; t < TSEQ; t++) {
        const unsigned* hin = t ? (hs1 + (size_t)(t - 1) * BH) : zero;
        lstm_step<<<grid, NTHR>>>(nullptr, nullptr,
                                  x + t * INDIM, TSEQ * INDIM, eWih0,
                                  hin, w_eWhh0, ebih0, ebhh0,
                                  hs1 + (size_t)t * BH, c1, 0);
    }
    // Encoder layer 2 (mode 1): final state ends in h2b (T even)
    for (int t = 0; t < TSEQ; t++) {
        const unsigned* hin = (t == 0) ? zero : ((t & 1) ? h2a : h2b);
        unsigned* hout = (t & 1) ? h2b : h2a;
        lstm_step<<<grid, NTHR>>>(hs1 + (size_t)t * BH, w_eWih1,
                                  nullptr, 0, nullptr,
                                  hin, w_eWhh1, ebih1, ebhh1, hout, c2, 1);
    }
    // Decoder
    for (int s = 0; s < HOR; s++) {
        const unsigned* h1in = (s == 0) ? (hs1 + (size_t)(TSEQ - 1) * BH)
                                        : ((s & 1) ? h1a : h1b);
        unsigned* h1out = (s & 1) ? h1b : h1a;
        lstm_step<<<grid, NTHR>>>(nullptr, nullptr,
                                  decin, INDIM, dWih0,
                                  h1in, w_dWhh0, dbih0, dbhh0, h1out, c1, 0);

        const unsigned* h2in = (s == 0) ? h2b : ((s & 1) ? h2a : h2b);
        unsigned* h2out = (s & 1) ? h2b : h2a;
        lstm_step<<<grid, NTHR>>>(h1out, w_dWih1,
                                  nullptr, 0, nullptr,
                                  h2in, w_dWhh1, dbih1, dbhh1, h2out, c2, 1);

        pred_kernel<<<BSZ / 4, 128>>>(h2out, fcW, fcb, out, s);
    }
}

// round 5
// speedup vs baseline: 2.3821x; 1.0889x over previous
#include <cuda_runtime.h>
#include <cuda_bf16.h>

// Problem dims
#define BSZ   512
#define HID   512
#define TSEQ  128
#define HOR   24
#define INDIM 2

// Tiling
#define BM    128     // batch rows per CTA
#define TH    16      // hidden cols per CTA (x4 quadrants = 64 gate cols)
#define BN    64
#define BK    32
#define NTHR  256
#define BH (BSZ*HID)
#define SROW  (BK+8)  // 40 elems = 80B rows: 16B-aligned, conflict-free ldmatrix

// ---------------- device scratch (static) ----------------------------------
// h-state as separate bf16 hi/lo planes (raw-copyable via cp.async)
__device__ __nv_bfloat16 g_hs1h[TSEQ*BH];
__device__ __nv_bfloat16 g_hs1l[TSEQ*BH];
__device__ __nv_bfloat16 g_h1ah[BH], g_h1al[BH], g_h1bh[BH], g_h1bl[BH];
__device__ __nv_bfloat16 g_h2ah[BH], g_h2al[BH], g_h2bh[BH], g_h2bl[BH];
__device__ __nv_bfloat16 g_zbf[BH];
__device__ float g_c1[BH], g_c2[BH];
__device__ float g_decin[BSZ*INDIM];
// split + tile-reordered weights: row = tile*64 + q*16 + hcd, col = k
// 0=eWhh0 1=eWih1 2=eWhh1 3=dWhh0 4=dWih1 5=dWhh1
__device__ __nv_bfloat16 g_wh[6][4*HID*HID];
__device__ __nv_bfloat16 g_wl[6][4*HID*HID];

struct Stage {
    __nv_bfloat16 Ah[BM][SROW];
    __nv_bfloat16 Al[BM][SROW];
    __nv_bfloat16 Wh[BN][SROW];
    __nv_bfloat16 Wl[BN][SROW];
};
#define SMEM_BYTES (2 * (int)sizeof(Stage))   // 61440 > epilogue's 34816

__device__ __forceinline__ float fast_sigmoid(float x) {
    return 1.0f / (1.0f + __expf(-x));
}
__device__ __forceinline__ float fast_tanh(float x) {
    return 1.0f - 2.0f / (__expf(2.0f * x) + 1.0f);
}

__device__ __forceinline__ void mma_bf16(float* c, const unsigned* a, const unsigned* b) {
    asm volatile(
        "mma.sync.aligned.m16n8k16.row.col.f32.bf16.bf16.f32 "
        "{%0,%1,%2,%3}, {%4,%5,%6,%7}, {%8,%9}, {%0,%1,%2,%3};\n"
        : "+f"(c[0]), "+f"(c[1]), "+f"(c[2]), "+f"(c[3])
        : "r"(a[0]), "r"(a[1]), "r"(a[2]), "r"(a[3]), "r"(b[0]), "r"(b[1]));
}
__device__ __forceinline__ void ldsm4(unsigned* r, const void* p) {
    unsigned addr = (unsigned)__cvta_generic_to_shared(p);
    asm volatile("ldmatrix.sync.aligned.m8n8.x4.shared.b16 {%0,%1,%2,%3}, [%4];"
        : "=r"(r[0]), "=r"(r[1]), "=r"(r[2]), "=r"(r[3]) : "r"(addr));
}
__device__ __forceinline__ void cp16(void* smem, const void* gmem) {
    unsigned s = (unsigned)__cvta_generic_to_shared(smem);
    asm volatile("cp.async.cg.shared.global [%0], [%1], 16;\n" :: "r"(s), "l"(gmem));
}
__device__ __forceinline__ void cp_commit() {
    asm volatile("cp.async.commit_group;\n");
}
template<int N> __device__ __forceinline__ void cp_wait() {
    asm volatile("cp.async.wait_group %0;\n" :: "n"(N));
}

// acc += A[b0+..,:] @ Wt^T over K=HID, 3-pass bf16 split, cp.async 2-stage pipe.
// Ah/Al: [*, 512] bf16 planes. Wh/Wl: tile-reordered [64, 512] (tile pre-offset).
__device__ __forceinline__ void gemm_planes(
    const __nv_bfloat16* __restrict__ Ah, const __nv_bfloat16* __restrict__ Al,
    const __nv_bfloat16* __restrict__ Wh, const __nv_bfloat16* __restrict__ Wl,
    int b0, float acc[2][4][4], Stage* st)
{
    const int tid = threadIdx.x;
    const int wid = tid >> 5, lane = tid & 31;
    const int wm = wid >> 1, wn = wid & 1;
    const int a_row = (lane & 7) + ((lane >> 3) & 1) * 8;
    const int a_col = (lane >> 4) * 8;
    const int b_row = (lane >> 4) * 8 + (lane & 7);
    const int b_col = ((lane >> 3) & 1) * 8;

    auto load = [&](int s, int k0) {
        #pragma unroll
        for (int i = 0; i < 2; i++) {
            int idx = tid + i * NTHR;           // 0..511 over 128 rows x 4 chunks
            int r = idx >> 2, c = (idx & 3) * 8;
            cp16(&st[s].Ah[r][c], Ah + (b0 + r) * HID + k0 + c);
            cp16(&st[s].Al[r][c], Al + (b0 + r) * HID + k0 + c);
        }
        {
            int r = tid >> 2, c = (tid & 3) * 8;  // 64 rows x 4 chunks
            cp16(&st[s].Wh[r][c], Wh + r * HID + k0 + c);
            cp16(&st[s].Wl[r][c], Wl + r * HID + k0 + c);
        }
        cp_commit();
    };

    load(0, 0);
    int s = 0;
    #pragma unroll 1
    for (int it = 0; it < HID / BK; it++) {
        if (it + 1 < HID / BK) { load(s ^ 1, (it + 1) * BK); cp_wait<1>(); }
        else cp_wait<0>();
        __syncthreads();
        #pragma unroll
        for (int kk = 0; kk < 2; kk++) {
            unsigned ah[2][4], al[2][4], bh[2][4], bl[2][4];
            #pragma unroll
            for (int mt = 0; mt < 2; mt++) {
                ldsm4(ah[mt], &st[s].Ah[wm * 32 + mt * 16 + a_row][kk * 16 + a_col]);
                ldsm4(al[mt], &st[s].Al[wm * 32 + mt * 16 + a_row][kk * 16 + a_col]);
            }
            #pragma unroll
            for (int p = 0; p < 2; p++) {
                ldsm4(bh[p], &st[s].Wh[wn * 32 + p * 16 + b_row][kk * 16 + b_col]);
                ldsm4(bl[p], &st[s].Wl[wn * 32 + p * 16 + b_row][kk * 16 + b_col]);
            }
            #pragma unroll
            for (int mt = 0; mt < 2; mt++)
                #pragma unroll
                for (int nb = 0; nb < 4; nb++) {
                    const unsigned* B2h = &bh[nb >> 1][(nb & 1) * 2];
                    const unsigned* B2l = &bl[nb >> 1][(nb & 1) * 2];
                    mma_bf16(acc[mt][nb], ah[mt], B2h);
                    mma_bf16(acc[mt][nb], ah[mt], B2l);
                    mma_bf16(acc[mt][nb], al[mt], B2h);
                }
        }
        __syncthreads();
        s ^= 1;
    }
}

// One fused LSTM step.
// mode 0: input projection via K=2 scalar epilogue (x1 fp32, Wx fp32 [2048,2]).
// mode 1: input projection via full K=512 GEMM on (A1h/A1l, W1h/W1l).
__global__ void __launch_bounds__(NTHR, 1)
lstm_step(const __nv_bfloat16* __restrict__ A1h, const __nv_bfloat16* __restrict__ A1l,
          const __nv_bfloat16* __restrict__ W1h, const __nv_bfloat16* __restrict__ W1l,
          const float* __restrict__ x1, int lda1, const float* __restrict__ Wx,
          const __nv_bfloat16* __restrict__ Hinh, const __nv_bfloat16* __restrict__ Hinl,
          const __nv_bfloat16* __restrict__ Whh_h, const __nv_bfloat16* __restrict__ Whh_l,
          const float* __restrict__ bih, const float* __restrict__ bhh,
          __nv_bfloat16* __restrict__ Houth, __nv_bfloat16* __restrict__ Houtl,
          float* __restrict__ C, int mode)
{
    extern __shared__ char smem_raw[];
    Stage* st = reinterpret_cast<Stage*>(smem_raw);
    float (*gm)[BN + 4] = reinterpret_cast<float (*)[BN + 4]>(smem_raw);

    const int tid = threadIdx.x;
    const int wid = tid >> 5, lane = tid & 31;
    const int wm = wid >> 1, wn = wid & 1;
    const int hc0 = blockIdx.x * TH;
    const int b0  = blockIdx.y * BM;
    const int wtile = blockIdx.x * BN * HID;   // weight tile offset

    float acc[2][4][4];
    #pragma unroll
    for (int mt = 0; mt < 2; mt++)
        #pragma unroll
        for (int nb = 0; nb < 4; nb++)
            #pragma unroll
            for (int r = 0; r < 4; r++) acc[mt][nb][r] = 0.0f;

    if (mode == 1) gemm_planes(A1h, A1l, W1h + wtile, W1l + wtile, b0, acc, st);
    gemm_planes(Hinh, Hinl, Whh_h + wtile, Whh_l + wtile, b0, acc, st);

    // ---- epilogue: gate transpose through smem, then fused cell update ----
    {
        int g = lane >> 2, t = lane & 3;
        #pragma unroll
        for (int mt = 0; mt < 2; mt++)
            #pragma unroll
            for (int nb = 0; nb < 4; nb++) {
                int row = wm * 32 + mt * 16 + g;
                int col = wn * 32 + nb * 8 + t * 2;
                gm[row][col]         = acc[mt][nb][0];
                gm[row][col + 1]     = acc[mt][nb][1];
                gm[row + 8][col]     = acc[mt][nb][2];
                gm[row + 8][col + 1] = acc[mt][nb][3];
            }
    }
    __syncthreads();
    #pragma unroll
    for (int i = 0; i < 8; i++) {
        int idx = tid + i * NTHR;      // 0..2047 over 128 batch x 16 hc
        int hcd = idx & 15, br = idx >> 4;
        int b = b0 + br, hc = hc0 + hcd;
        float gv[4];
        #pragma unroll
        for (int q = 0; q < 4; q++)
            gv[q] = gm[br][q * 16 + hcd] + bih[q * HID + hc] + bhh[q * HID + hc];
        if (mode == 0) {
            float xi0 = x1[b * lda1 + 0];
            float xi1 = x1[b * lda1 + 1];
            #pragma unroll
            for (int q = 0; q < 4; q++) {
                int gg = q * HID + hc;
                gv[q] += xi0 * Wx[gg * INDIM + 0] + xi1 * Wx[gg * INDIM + 1];
            }
        }
        float ig = fast_sigmoid(gv[0]);
        float fg = fast_sigmoid(gv[1]);
        float gg = fast_tanh(gv[2]);
        float og = fast_sigmoid(gv[3]);
        int ci = b * HID + hc;
        float c = C[ci];
        c = fg * c + ig * gg;
        C[ci] = c;
        float h = og * fast_tanh(c);
        __nv_bfloat16 hh = __float2bfloat16(h);
        float resid = h - __bfloat162float(hh);
        Houth[ci] = hh;
        Houtl[ci] = __float2bfloat16(resid);
    }
}

// Split fp32 weights [2048,512] into tile-reordered bf16 hi/lo planes:
// dst row = tile*64 + q*16 + hcd  (tile = hc/16), col = k.
__global__ void convert_w(const float* __restrict__ src,
                          __nv_bfloat16* __restrict__ dh,
                          __nv_bfloat16* __restrict__ dl, int n)
{
    int i = blockIdx.x * blockDim.x + threadIdx.x;
    if (i < n) {
        int g = i >> 9, k = i & 511;
        int q = g >> 9, hc = g & 511;
        int tile = hc >> 4, hcd = hc & 15;
        int dr = ((tile * 4 + q) * 16 + hcd) * HID + k;
        float w = src[i];
        __nv_bfloat16 h = __float2bfloat16(w);
        dh[dr] = h;
        dl[dr] = __float2bfloat16(w - __bfloat162float(h));
    }
}

// pred[b,k] = (hi+lo)(h2[b,:]) . fcW[k,:] + fcb[k]
__global__ void pred_kernel(const __nv_bfloat16* __restrict__ h2h,
                            const __nv_bfloat16* __restrict__ h2l,
                            const float* __restrict__ fcW,
                            const float* __restrict__ fcb,
                            float* __restrict__ out, int s)
{
    int warp = threadIdx.x >> 5;
    int lane = threadIdx.x & 31;
    int b = blockIdx.x * 4 + warp;
    float a0 = 0.0f, a1 = 0.0f;
    #pragma unroll
    for (int j = lane; j < HID; j += 32) {
        float h = __bfloat162float(h2h[b * HID + j]) + __bfloat162float(h2l[b * HID + j]);
        a0 += h * fcW[j];
        a1 += h * fcW[HID + j];
    }
    #pragma unroll
    for (int o = 16; o; o >>= 1) {
        a0 += __shfl_xor_sync(0xffffffffu, a0, o);
        a1 += __shfl_xor_sync(0xffffffffu, a1, o);
    }
    if (lane == 0) {
        float p0 = a0 + fcb[0], p1 = a1 + fcb[1];
        out[b * HOR * 2 + s * 2 + 0] = p0;
        out[b * HOR * 2 + s * 2 + 1] = p1;
        g_decin[b * 2 + 0] = p0;
        g_decin[b * 2 + 1] = p1;
    }
}

__global__ void zero_init() {
    int i = blockIdx.x * blockDim.x + threadIdx.x;
    if (i < BH) {
        g_zbf[i] = __ushort_as_bfloat16((unsigned short)0);
        g_c1[i] = 0.0f;
        g_c2[i] = 0.0f;
    }
    if (i < BSZ * INDIM) g_decin[i] = 0.0f;
}

extern "C" void kernel_launch(void* const* d_in, const int* in_sizes, int n_in,
                              void* d_out, int out_size)
{
    const float* x      = (const float*)d_in[0];
    const float* eWih0  = (const float*)d_in[1];
    const float* eWhh0  = (const float*)d_in[2];
    const float* ebih0  = (const float*)d_in[3];
    const float* ebhh0  = (const float*)d_in[4];
    const float* eWih1  = (const float*)d_in[5];
    const float* eWhh1  = (const float*)d_in[6];
    const float* ebih1  = (const float*)d_in[7];
    const float* ebhh1  = (const float*)d_in[8];
    const float* dWih0  = (const float*)d_in[9];
    const float* dWhh0  = (const float*)d_in[10];
    const float* dbih0  = (const float*)d_in[11];
    const float* dbhh0  = (const float*)d_in[12];
    const float* dWih1  = (const float*)d_in[13];
    const float* dWhh1  = (const float*)d_in[14];
    const float* dbih1  = (const float*)d_in[15];
    const float* dbhh1  = (const float*)d_in[16];
    const float* fcW    = (const float*)d_in[17];
    const float* fcb    = (const float*)d_in[18];
    float* out = (float*)d_out;

    __nv_bfloat16 *hs1h, *hs1l, *h1ah, *h1al, *h1bh, *h1bl;
    __nv_bfloat16 *h2ah, *h2al, *h2bh, *h2bl, *zb, *whb, *wlb;
    float *c1, *c2, *decin;
    cudaGetSymbolAddress((void**)&hs1h, g_hs1h);
    cudaGetSymbolAddress((void**)&hs1l, g_hs1l);
    cudaGetSymbolAddress((void**)&h1ah, g_h1ah);
    cudaGetSymbolAddress((void**)&h1al, g_h1al);
    cudaGetSymbolAddress((void**)&h1bh, g_h1bh);
    cudaGetSymbolAddress((void**)&h1bl, g_h1bl);
    cudaGetSymbolAddress((void**)&h2ah, g_h2ah);
    cudaGetSymbolAddress((void**)&h2al, g_h2al);
    cudaGetSymbolAddress((void**)&h2bh, g_h2bh);
    cudaGetSymbolAddress((void**)&h2bl, g_h2bl);
    cudaGetSymbolAddress((void**)&zb,   g_zbf);
    cudaGetSymbolAddress((void**)&whb,  g_wh);
    cudaGetSymbolAddress((void**)&wlb,  g_wl);
    cudaGetSymbolAddress((void**)&c1,   g_c1);
    cudaGetSymbolAddress((void**)&c2,   g_c2);
    cudaGetSymbolAddress((void**)&decin, g_decin);

    const int WSZ = 4 * HID * HID;
    __nv_bfloat16 *wh_eWhh0 = whb + 0 * WSZ, *wl_eWhh0 = wlb + 0 * WSZ;
    __nv_bfloat16 *wh_eWih1 = whb + 1 * WSZ, *wl_eWih1 = wlb + 1 * WSZ;
    __nv_bfloat16 *wh_eWhh1 = whb + 2 * WSZ, *wl_eWhh1 = wlb + 2 * WSZ;
    __nv_bfloat16 *wh_dWhh0 = whb + 3 * WSZ, *wl_dWhh0 = wlb + 3 * WSZ;
    __nv_bfloat16 *wh_dWih1 = whb + 4 * WSZ, *wl_dWih1 = wlb + 4 * WSZ;
    __nv_bfloat16 *wh_dWhh1 = whb + 5 * WSZ, *wl_dWhh1 = wlb + 5 * WSZ;

    cudaFuncSetAttribute(lstm_step, cudaFuncAttributeMaxDynamicSharedMemorySize,
                         SMEM_BYTES);

    zero_init<<<(BH + 255) / 256, 256>>>();
    {
        int nb = (WSZ + 255) / 256;
        convert_w<<<nb, 256>>>(eWhh0, wh_eWhh0, wl_eWhh0, WSZ);
        convert_w<<<nb, 256>>>(eWih1, wh_eWih1, wl_eWih1, WSZ);
        convert_w<<<nb, 256>>>(eWhh1, wh_eWhh1, wl_eWhh1, WSZ);
        convert_w<<<nb, 256>>>(dWhh0, wh_dWhh0, wl_dWhh0, WSZ);
        convert_w<<<nb, 256>>>(dWih1, wh_dWih1, wl_dWih1, WSZ);
        convert_w<<<nb, 256>>>(dWhh1, wh_dWhh1, wl_dWhh1, WSZ);
    }

    dim3 grid(HID / TH, BSZ / BM);   // (32, 4) = 128 CTAs

    // Encoder layer 1 (mode 0). h chain lives in hs1 planes.
    for (int t = 0; t < TSEQ; t++) {
        const __nv_bfloat16* hinh = t ? (hs1h + (size_t)(t - 1) * BH) : zb;
        const __nv_bfloat16* hinl = t ? (hs1l + (size_t)(t - 1) * BH) : zb;
        lstm_step<<<grid, NTHR, SMEM_BYTES>>>(
            nullptr, nullptr, nullptr, nullptr,
            x + t * INDIM, TSEQ * INDIM, eWih0,
            hinh, hinl, wh_eWhh0, wl_eWhh0, ebih0, ebhh0,
            hs1h + (size_t)t * BH, hs1l + (size_t)t * BH, c1, 0);
    }
    // Encoder layer 2 (mode 1): final state ends in h2b (T even)
    for (int t = 0; t < TSEQ; t++) {
        const __nv_bfloat16* hinh = (t == 0) ? zb : ((t & 1) ? h2ah : h2bh);
        const __nv_bfloat16* hinl = (t == 0) ? zb : ((t & 1) ? h2al : h2bl);
        __nv_bfloat16* houth = (t & 1) ? h2bh : h2ah;
        __nv_bfloat16* houtl = (t & 1) ? h2bl : h2al;
        lstm_step<<<grid, NTHR, SMEM_BYTES>>>(
            hs1h + (size_t)t * BH, hs1l + (size_t)t * BH, wh_eWih1, wl_eWih1,
            nullptr, 0, nullptr,
            hinh, hinl, wh_eWhh1, wl_eWhh1, ebih1, ebhh1, houth, houtl, c2, 1);
    }
    // Decoder
    for (int s = 0; s < HOR; s++) {
        const __nv_bfloat16* h1inh = (s == 0) ? (hs1h + (size_t)(TSEQ - 1) * BH)
                                              : ((s & 1) ? h1ah : h1bh);
        const __nv_bfloat16* h1inl = (s == 0) ? (hs1l + (size_t)(TSEQ - 1) * BH)
                                              : ((s & 1) ? h1al : h1bl);
        __nv_bfloat16* h1outh = (s & 1) ? h1bh : h1ah;
        __nv_bfloat16* h1outl = (s & 1) ? h1bl : h1al;
        lstm_step<<<grid, NTHR, SMEM_BYTES>>>(
            nullptr, nullptr, nullptr, nullptr,
            decin, INDIM, dWih0,
            h1inh, h1inl, wh_dWhh0, wl_dWhh0, dbih0, dbhh0, h1outh, h1outl, c1, 0);

        const __nv_bfloat16* h2inh = (s == 0) ? h2bh : ((s & 1) ? h2ah : h2bh);
        const __nv_bfloat16* h2inl = (s == 0) ? h2bl : ((s & 1) ? h2al : h2bl);
        __nv_bfloat16* h2outh = (s & 1) ? h2bh : h2ah;
        __nv_bfloat16* h2outl = (s & 1) ? h2bl : h2al;
        lstm_step<<<grid, NTHR, SMEM_BYTES>>>(
            h1outh, h1outl, wh_dWih1, wl_dWih1,
            nullptr, 0, nullptr,
            h2inh, h2inl, wh_dWhh1, wl_dWhh1, dbih1, dbhh1, h2outh, h2outl, c2, 1);

        pred_kernel<<<BSZ / 4, 128>>>(h2outh, h2outl, fcW, fcb, out, s);
    }
}

// round 7
// speedup vs baseline: 2.6939x; 1.1309x over previous
#include <cuda_runtime.h>
#include <cuda_bf16.h>
#include <cstdint>

// Problem dims
#define BSZ   512
#define HID   512
#define TSEQ  128
#define HOR   24
#define INDIM 2

// Tiling
#define BM    128     // batch rows per CTA
#define BN    64      // gate cols per CTA = 4 quadrants x 16 hidden cols
#define BK    64      // k-chunk per pipeline iter
#define NTHR  256
#define BH (BSZ*HID)
#define SROW  72      // padded smem row: 64 + 8 bf16 = 144B, conflict-free ldmatrix

// 4-stage smem ring
#define STAGES      4
#define A_PLANE     (BM*SROW*2)            // 18432 B
#define B_PLANE     (BN*SROW*2)            // 9216 B
#define SM_AH       0
#define SM_AL       (A_PLANE)
#define SM_BHI      (2*A_PLANE)
#define SM_BLO      (2*A_PLANE + B_PLANE)
#define STAGE_BYTES (2*A_PLANE + 2*B_PLANE)   // 55296
#define SMEM_DYN    (STAGES*STAGE_BYTES)      // 221184

// ---------------- device scratch (static) ----------------------------------
__device__ __nv_bfloat16 g_hs1h[TSEQ*BH];
__device__ __nv_bfloat16 g_hs1l[TSEQ*BH];
__device__ __nv_bfloat16 g_h1ah[BH], g_h1al[BH], g_h1bh[BH], g_h1bl[BH];
__device__ __nv_bfloat16 g_h2ah[BH], g_h2al[BH], g_h2bh[BH], g_h2bl[BH];
__device__ __nv_bfloat16 g_zbf[BH];
__device__ float g_c1[BH], g_c2[BH];
__device__ float g_decin[BSZ*INDIM];
// split + tile-reordered weights: row = tile*64 + q*16 + hcd, col = k
// 0=eWhh0 1=eWih1 2=eWhh1 3=dWhh0 4=dWih1 5=dWhh1
__device__ __nv_bfloat16 g_wh[6][4*HID*HID];
__device__ __nv_bfloat16 g_wl[6][4*HID*HID];
// combined biases bih+bhh: 0=enc0 1=enc1 2=dec0 3=dec1
__device__ float g_bsum[4][4*HID];

// ---------------- helpers ---------------------------------------------------
__device__ __forceinline__ float fast_sigmoid(float x) {
    return 1.0f / (1.0f + __expf(-x));
}
__device__ __forceinline__ float fast_tanh(float x) {
    return 1.0f - 2.0f / (__expf(2.0f * x) + 1.0f);
}
__device__ __forceinline__ void mma_bf16(float* c, const unsigned* a, const unsigned* b) {
    asm volatile(
        "mma.sync.aligned.m16n8k16.row.col.f32.bf16.bf16.f32 "
        "{%0,%1,%2,%3}, {%4,%5,%6,%7}, {%8,%9}, {%0,%1,%2,%3};\n"
        : "+f"(c[0]), "+f"(c[1]), "+f"(c[2]), "+f"(c[3])
        : "r"(a[0]), "r"(a[1]), "r"(a[2]), "r"(a[3]), "r"(b[0]), "r"(b[1]));
}
__device__ __forceinline__ void ldsm4(unsigned* r, const void* p) {
    unsigned addr = (unsigned)__cvta_generic_to_shared(p);
    asm volatile("ldmatrix.sync.aligned.m8n8.x4.shared.b16 {%0,%1,%2,%3}, [%4];"
        : "=r"(r[0]), "=r"(r[1]), "=r"(r[2]), "=r"(r[3]) : "r"(addr));
}
__device__ __forceinline__ void cp16(void* smem, const void* gmem) {
    unsigned s = (unsigned)__cvta_generic_to_shared(smem);
    asm volatile("cp.async.cg.shared.global [%0], [%1], 16;\n" :: "r"(s), "l"(gmem));
}
__device__ __forceinline__ void cp_commit() {
    asm volatile("cp.async.commit_group;\n");
}
template<int N> __device__ __forceinline__ void cp_wait() {
    asm volatile("cp.async.wait_group %0;\n" :: "n"(N));
}

// Stage one (A 128xBK, W 64xBK) hi/lo tile set into ring buffer `buf`.
__device__ __forceinline__ void stage_tiles(
    char* smem, int buf,
    const __nv_bfloat16* __restrict__ Ah, const __nv_bfloat16* __restrict__ Al,
    const __nv_bfloat16* __restrict__ Wh, const __nv_bfloat16* __restrict__ Wl,
    int b0, int k0)
{
    char* base = smem + buf * STAGE_BYTES;
    const int tid = threadIdx.x;
    #pragma unroll
    for (int i = 0; i < 4; i++) {
        int idx = tid + i * NTHR;        // 0..1023 = 128 rows x 8 chunks of 16B
        int row = idx >> 3, ch = idx & 7;
        int so = (row * SROW + ch * 8) * 2;
        const int go = (b0 + row) * HID + k0 + ch * 8;
        cp16(base + SM_AH + so, Ah + go);
        cp16(base + SM_AL + so, Al + go);
    }
    #pragma unroll
    for (int i = 0; i < 2; i++) {
        int idx = tid + i * NTHR;        // 0..511 = 64 rows x 8 chunks
        int row = idx >> 3, ch = idx & 7;
        int so = (row * SROW + ch * 8) * 2;
        const int go = row * HID + k0 + ch * 8;
        cp16(base + SM_BHI + so, Wh + go);
        cp16(base + SM_BLO + so, Wl + go);
    }
    cp_commit();
}

// ---------------- fused LSTM step (mma.sync, 3-pass bf16 split) -------------
// mode 0: input proj via K=2 scalar epilogue (x1 fp32, Wx fp32 [2048,2]); NI=8
// mode 1: input proj via full K=512 GEMM on (A1h/A1l, W1h/W1l); NI=16
__global__ void __launch_bounds__(NTHR)
lstm_step(const __nv_bfloat16* __restrict__ A1h, const __nv_bfloat16* __restrict__ A1l,
          const __nv_bfloat16* __restrict__ W1h, const __nv_bfloat16* __restrict__ W1l,
          const float* __restrict__ x1, int lda1, const float* __restrict__ Wx,
          const __nv_bfloat16* __restrict__ Hinh, const __nv_bfloat16* __restrict__ Hinl,
          const __nv_bfloat16* __restrict__ Whh_h, const __nv_bfloat16* __restrict__ Whh_l,
          const float* __restrict__ bsum,
          __nv_bfloat16* __restrict__ Houth, __nv_bfloat16* __restrict__ Houtl,
          float* __restrict__ C, int mode)
{
    extern __shared__ char smem[];
    const int tid = threadIdx.x;
    const int wid = tid >> 5, lane = tid & 31;
    const int wm = wid >> 1, wn = wid & 1;
    const int hc0 = blockIdx.x * 16;
    const int b0  = blockIdx.y * BM;
    const int wt  = blockIdx.x * BN * HID;   // weight tile offset
    const int NI  = (mode == 1) ? 16 : 8;

    // ldmatrix lane addressing (byte offsets within a plane)
    const int a_row = (lane & 7) + ((lane >> 3) & 1) * 8;
    const int a_col = (lane >> 4) * 8;
    const int b_row = (lane >> 4) * 8 + (lane & 7);
    const int b_col = ((lane >> 3) & 1) * 8;

    auto srcs = [&](int j, const __nv_bfloat16*& sAh, const __nv_bfloat16*& sAl,
                    const __nv_bfloat16*& sWh, const __nv_bfloat16*& sWl, int& k0) {
        if (mode == 1 && j < 8) {
            sAh = A1h; sAl = A1l; sWh = W1h + wt; sWl = W1l + wt; k0 = j * BK;
        } else {
            int jj = (mode == 1) ? j - 8 : j;
            sAh = Hinh; sAl = Hinl; sWh = Whh_h + wt; sWl = Whh_l + wt; k0 = jj * BK;
        }
    };

    float acc[2][4][4];
    #pragma unroll
    for (int mt = 0; mt < 2; mt++)
        #pragma unroll
        for (int nb = 0; nb < 4; nb++)
            #pragma unroll
            for (int r = 0; r < 4; r++) acc[mt][nb][r] = 0.0f;

    // prologue: fill 3 of the 4 ring slots
    #pragma unroll
    for (int p = 0; p < 3; p++) {
        const __nv_bfloat16 *a, *al, *w, *wl; int k0;
        srcs(p, a, al, w, wl, k0);
        stage_tiles(smem, p, a, al, w, wl, b0, k0);
    }

    #pragma unroll 1
    for (int it = 0; it < NI; it++) {
        // complete cp.async group `it`
        if (NI - it >= 3)       cp_wait<2>();
        else if (NI - it == 2)  cp_wait<1>();
        else                    cp_wait<0>();
        __syncthreads();   // all warps see stage it; all done reading stage it-1
        if (it + 3 < NI) {
            const __nv_bfloat16 *a, *al, *w, *wl; int k0;
            srcs(it + 3, a, al, w, wl, k0);
            stage_tiles(smem, (it + 3) & 3, a, al, w, wl, b0, k0);
        }
        char* base = smem + (it & 3) * STAGE_BYTES;
        #pragma unroll
        for (int kk = 0; kk < 4; kk++) {
            unsigned ah[2][4], al[2][4], bh[2][4], bl[2][4];
            #pragma unroll
            for (int mt = 0; mt < 2; mt++) {
                int off = ((wm * 32 + mt * 16 + a_row) * SROW + kk * 16 + a_col) * 2;
                ldsm4(ah[mt], base + SM_AH + off);
                ldsm4(al[mt], base + SM_AL + off);
            }
            #pragma unroll
            for (int p = 0; p < 2; p++) {
                int off = ((wn * 32 + p * 16 + b_row) * SROW + kk * 16 + b_col) * 2;
                ldsm4(bh[p], base + SM_BHI + off);
                ldsm4(bl[p], base + SM_BLO + off);
            }
            // pass-major: spaces same-accumulator HMMAs by 8 issues
            #pragma unroll
            for (int mt = 0; mt < 2; mt++)
                #pragma unroll
                for (int nb = 0; nb < 4; nb++)
                    mma_bf16(acc[mt][nb], ah[mt], &bh[nb >> 1][(nb & 1) * 2]);
            #pragma unroll
            for (int mt = 0; mt < 2; mt++)
                #pragma unroll
                for (int nb = 0; nb < 4; nb++)
                    mma_bf16(acc[mt][nb], ah[mt], &bl[nb >> 1][(nb & 1) * 2]);
            #pragma unroll
            for (int mt = 0; mt < 2; mt++)
                #pragma unroll
                for (int nb = 0; nb < 4; nb++)
                    mma_bf16(acc[mt][nb], al[mt], &bh[nb >> 1][(nb & 1) * 2]);
        }
    }

    // ---- epilogue: gate transpose through smem, then fused cell update ----
    float (*gm)[BN + 4] = reinterpret_cast<float (*)[BN + 4]>(smem);
    __syncthreads();
    {
        int g = lane >> 2, t = lane & 3;
        #pragma unroll
        for (int mt = 0; mt < 2; mt++)
            #pragma unroll
            for (int nb = 0; nb < 4; nb++) {
                int row = wm * 32 + mt * 16 + g;
                int col = wn * 32 + nb * 8 + t * 2;
                gm[row][col]         = acc[mt][nb][0];
                gm[row][col + 1]     = acc[mt][nb][1];
                gm[row + 8][col]     = acc[mt][nb][2];
                gm[row + 8][col + 1] = acc[mt][nb][3];
            }
    }
    __syncthreads();
    #pragma unroll
    for (int i = 0; i < 8; i++) {
        int idx = tid + i * NTHR;      // 0..2047 over 128 batch x 16 hc
        int hcd = idx & 15, br = idx >> 4;
        int b = b0 + br, hc = hc0 + hcd;
        float gv[4];
        #pragma unroll
        for (int q = 0; q < 4; q++)
            gv[q] = gm[br][q * 16 + hcd] + bsum[q * HID + hc];
        if (mode == 0) {
            float xi0 = x1[b * lda1 + 0];
            float xi1 = x1[b * lda1 + 1];
            #pragma unroll
            for (int q = 0; q < 4; q++) {
                int gg = q * HID + hc;
                gv[q] += xi0 * Wx[gg * INDIM + 0] + xi1 * Wx[gg * INDIM + 1];
            }
        }
        float ig = fast_sigmoid(gv[0]);
        float fg = fast_sigmoid(gv[1]);
        float gg = fast_tanh(gv[2]);
        float og = fast_sigmoid(gv[3]);
        int ci = b * HID + hc;
        float c = C[ci];
        c = fg * c + ig * gg;
        C[ci] = c;
        float h = og * fast_tanh(c);
        __nv_bfloat16 hh = __float2bfloat16(h);
        Houth[ci] = hh;
        Houtl[ci] = __float2bfloat16(h - __bfloat162float(hh));
    }
}

// One fused conversion kernel: 6 weight matrices -> split/tile-reordered planes.
// Block-contiguous per matrix: 4096 blocks per matrix (WSZ = 2^20).
__global__ void convert_all(const float* __restrict__ s0, const float* __restrict__ s1,
                            const float* __restrict__ s2, const float* __restrict__ s3,
                            const float* __restrict__ s4, const float* __restrict__ s5,
                            __nv_bfloat16* __restrict__ dhb,
                            __nv_bfloat16* __restrict__ dlb)
{
    const int WSZ = 4 * HID * HID;
    int m = blockIdx.x >> 12;                    // matrix index 0..5
    int j = ((blockIdx.x & 4095) << 8) + threadIdx.x;   // 0..WSZ-1
    const float* src;
    switch (m) {
        case 0: src = s0; break;
        case 1: src = s1; break;
        case 2: src = s2; break;
        case 3: src = s3; break;
        case 4: src = s4; break;
        default: src = s5; break;
    }
    int g = j >> 9, k = j & 511;
    int q = g >> 9, hc = g & 511;
    int tile = hc >> 4, hcd = hc & 15;
    int dr = m * WSZ + ((tile * 4 + q) * 16 + hcd) * HID + k;
    float w = src[j];
    __nv_bfloat16 h = __float2bfloat16(w);
    dhb[dr] = h;
    dlb[dr] = __float2bfloat16(w - __bfloat162float(h));
}

// Fused init: zero states + combined biases.
__global__ void setup_init(const float* __restrict__ eb0a, const float* __restrict__ eb0b,
                           const float* __restrict__ eb1a, const float* __restrict__ eb1b,
                           const float* __restrict__ db0a, const float* __restrict__ db0b,
                           const float* __restrict__ db1a, const float* __restrict__ db1b)
{
    int i = blockIdx.x * blockDim.x + threadIdx.x;
    if (i < BH) {
        g_zbf[i] = __ushort_as_bfloat16((unsigned short)0);
        g_c1[i] = 0.0f;
        g_c2[i] = 0.0f;
    }
    if (i < BSZ * INDIM) g_decin[i] = 0.0f;
    if (i < 4 * HID) {
        g_bsum[0][i] = eb0a[i] + eb0b[i];
        g_bsum[1][i] = eb1a[i] + eb1b[i];
        g_bsum[2][i] = db0a[i] + db0b[i];
        g_bsum[3][i] = db1a[i] + db1b[i];
    }
}

// pred[b,k] = (hi+lo)(h2[b,:]) . fcW[k,:] + fcb[k]
__global__ void pred_kernel(const __nv_bfloat16* __restrict__ h2h,
                            const __nv_bfloat16* __restrict__ h2l,
                            const float* __restrict__ fcW,
                            const float* __restrict__ fcb,
                            float* __restrict__ out, int s)
{
    int warp = threadIdx.x >> 5;
    int lane = threadIdx.x & 31;
    int b = blockIdx.x * 4 + warp;
    float a0 = 0.0f, a1 = 0.0f;
    #pragma unroll
    for (int j = lane; j < HID; j += 32) {
        float h = __bfloat162float(h2h[b * HID + j]) + __bfloat162float(h2l[b * HID + j]);
        a0 += h * fcW[j];
        a1 += h * fcW[HID + j];
    }
    #pragma unroll
    for (int o = 16; o; o >>= 1) {
        a0 += __shfl_xor_sync(0xffffffffu, a0, o);
        a1 += __shfl_xor_sync(0xffffffffu, a1, o);
    }
    if (lane == 0) {
        float p0 = a0 + fcb[0], p1 = a1 + fcb[1];
        out[b * HOR * 2 + s * 2 + 0] = p0;
        out[b * HOR * 2 + s * 2 + 1] = p1;
        g_decin[b * 2 + 0] = p0;
        g_decin[b * 2 + 1] = p1;
    }
}

extern "C" void kernel_launch(void* const* d_in, const int* in_sizes, int n_in,
                              void* d_out, int out_size)
{
    const float* x      = (const float*)d_in[0];
    const float* eWih0  = (const float*)d_in[1];
    const float* eWhh0  = (const float*)d_in[2];
    const float* ebih0  = (const float*)d_in[3];
    const float* ebhh0  = (const float*)d_in[4];
    const float* eWih1  = (const float*)d_in[5];
    const float* eWhh1  = (const float*)d_in[6];
    const float* ebih1  = (const float*)d_in[7];
    const float* ebhh1  = (const float*)d_in[8];
    const float* dWih0  = (const float*)d_in[9];
    const float* dWhh0  = (const float*)d_in[10];
    const float* dbih0  = (const float*)d_in[11];
    const float* dbhh0  = (const float*)d_in[12];
    const float* dWih1  = (const float*)d_in[13];
    const float* dWhh1  = (const float*)d_in[14];
    const float* dbih1  = (const float*)d_in[15];
    const float* dbhh1  = (const float*)d_in[16];
    const float* fcW    = (const float*)d_in[17];
    const float* fcb    = (const float*)d_in[18];
    float* out = (float*)d_out;

    __nv_bfloat16 *hs1h, *hs1l, *h1ah, *h1al, *h1bh, *h1bl;
    __nv_bfloat16 *h2ah, *h2al, *h2bh, *h2bl, *zb, *whb, *wlb;
    float *c1, *c2, *decin, *bsb;
    cudaGetSymbolAddress((void**)&hs1h, g_hs1h);
    cudaGetSymbolAddress((void**)&hs1l, g_hs1l);
    cudaGetSymbolAddress((void**)&h1ah, g_h1ah);
    cudaGetSymbolAddress((void**)&h1al, g_h1al);
    cudaGetSymbolAddress((void**)&h1bh, g_h1bh);
    cudaGetSymbolAddress((void**)&h1bl, g_h1bl);
    cudaGetSymbolAddress((void**)&h2ah, g_h2ah);
    cudaGetSymbolAddress((void**)&h2al, g_h2al);
    cudaGetSymbolAddress((void**)&h2bh, g_h2bh);
    cudaGetSymbolAddress((void**)&h2bl, g_h2bl);
    cudaGetSymbolAddress((void**)&zb,   g_zbf);
    cudaGetSymbolAddress((void**)&whb,  g_wh);
    cudaGetSymbolAddress((void**)&wlb,  g_wl);
    cudaGetSymbolAddress((void**)&c1,   g_c1);
    cudaGetSymbolAddress((void**)&c2,   g_c2);
    cudaGetSymbolAddress((void**)&decin, g_decin);
    cudaGetSymbolAddress((void**)&bsb,  g_bsum);

    const int WSZ = 4 * HID * HID;
    __nv_bfloat16 *wh_eWhh0 = whb + 0 * WSZ, *wl_eWhh0 = wlb + 0 * WSZ;
    __nv_bfloat16 *wh_eWih1 = whb + 1 * WSZ, *wl_eWih1 = wlb + 1 * WSZ;
    __nv_bfloat16 *wh_eWhh1 = whb + 2 * WSZ, *wl_eWhh1 = wlb + 2 * WSZ;
    __nv_bfloat16 *wh_dWhh0 = whb + 3 * WSZ, *wl_dWhh0 = wlb + 3 * WSZ;
    __nv_bfloat16 *wh_dWih1 = whb + 4 * WSZ, *wl_dWih1 = wlb + 4 * WSZ;
    __nv_bfloat16 *wh_dWhh1 = whb + 5 * WSZ, *wl_dWhh1 = wlb + 5 * WSZ;
    float *bs_e0 = bsb + 0 * 4 * HID, *bs_e1 = bsb + 1 * 4 * HID;
    float *bs_d0 = bsb + 2 * 4 * HID, *bs_d1 = bsb + 3 * 4 * HID;

    cudaFuncSetAttribute(lstm_step, cudaFuncAttributeMaxDynamicSharedMemorySize,
                         SMEM_DYN);

    // 2 setup launches (keeps ncu's -s 5 window on lstm_step)
    setup_init<<<(BH + 255) / 256, 256>>>(ebih0, ebhh0, ebih1, ebhh1,
                                          dbih0, dbhh0, dbih1, dbhh1);
    convert_all<<<6 * 4096, 256>>>(eWhh0, eWih1, eWhh1, dWhh0, dWih1, dWhh1,
                                   whb, wlb);

    dim3 grid(HID / 16, BSZ / BM);   // (32, 4) = 128 CTAs

    // Encoder layer 1 (mode 0). h chain lives in hs1 planes.
    for (int t = 0; t < TSEQ; t++) {
        const __nv_bfloat16* hinh = t ? (hs1h + (size_t)(t - 1) * BH) : zb;
        const __nv_bfloat16* hinl = t ? (hs1l + (size_t)(t - 1) * BH) : zb;
        lstm_step<<<grid, NTHR, SMEM_DYN>>>(
            nullptr, nullptr, nullptr, nullptr,
            x + t * INDIM, TSEQ * INDIM, eWih0,
            hinh, hinl, wh_eWhh0, wl_eWhh0, bs_e0,
            hs1h + (size_t)t * BH, hs1l + (size_t)t * BH, c1, 0);
    }
    // Encoder layer 2 (mode 1): final state ends in h2b (T even)
    for (int t = 0; t < TSEQ; t++) {
        const __nv_bfloat16* hinh = (t == 0) ? zb : ((t & 1) ? h2ah : h2bh);
        const __nv_bfloat16* hinl = (t == 0) ? zb : ((t & 1) ? h2al : h2bl);
        __nv_bfloat16* houth = (t & 1) ? h2bh : h2ah;
        __nv_bfloat16* houtl = (t & 1) ? h2bl : h2al;
        lstm_step<<<grid, NTHR, SMEM_DYN>>>(
            hs1h + (size_t)t * BH, hs1l + (size_t)t * BH, wh_eWih1, wl_eWih1,
            nullptr, 0, nullptr,
            hinh, hinl, wh_eWhh1, wl_eWhh1, bs_e1, houth, houtl, c2, 1);
    }
    // Decoder
    for (int s = 0; s < HOR; s++) {
        const __nv_bfloat16* h1inh = (s == 0) ? (hs1h + (size_t)(TSEQ - 1) * BH)
                                              : ((s & 1) ? h1ah : h1bh);
        const __nv_bfloat16* h1inl = (s == 0) ? (hs1l + (size_t)(TSEQ - 1) * BH)
                                              : ((s & 1) ? h1al : h1bl);
        __nv_bfloat16* h1outh = (s & 1) ? h1bh : h1ah;
        __nv_bfloat16* h1outl = (s & 1) ? h1bl : h1al;
        lstm_step<<<grid, NTHR, SMEM_DYN>>>(
            nullptr, nullptr, nullptr, nullptr,
            decin, INDIM, dWih0,
            h1inh, h1inl, wh_dWhh0, wl_dWhh0, bs_d0, h1outh, h1outl, c1, 0);

        const __nv_bfloat16* h2inh = (s == 0) ? h2bh : ((s & 1) ? h2ah : h2bh);
        const __nv_bfloat16* h2inl = (s == 0) ? h2bl : ((s & 1) ? h2al : h2bl);
        __nv_bfloat16* h2outh = (s & 1) ? h2bh : h2ah;
        __nv_bfloat16* h2outl = (s & 1) ? h2bl : h2al;
        lstm_step<<<grid, NTHR, SMEM_DYN>>>(
            h1outh, h1outl, wh_dWih1, wl_dWih1,
            nullptr, 0, nullptr,
            h2inh, h2inl, wh_dWhh1, wl_dWhh1, bs_d1, h2outh, h2outl, c2, 1);

        pred_kernel<<<BSZ / 4, 128>>>(h2outh, h2outl, fcW, fcb, out, s);
    }
}

// round 8
// speedup vs baseline: 2.8791x; 1.0687x over previous
#include <cuda_runtime.h>
#include <cuda_bf16.h>
#include <cstdint>

// Problem dims
#define BSZ   512
#define HID   512
#define TSEQ  128
#define HOR   24
#define INDIM 2

// Tiling
#define BM    128     // batch rows per CTA
#define BN    64      // gate cols per CTA = 4 quadrants x 16 hidden cols
#define BK    64      // k-chunk per pipeline iter
#define NTHR  512     // 16 warps: 4x4 warp grid, warp tile 32x16
#define BH (BSZ*HID)
#define SROW  72      // padded smem row: 64 + 8 bf16 = 144B, conflict-free ldmatrix

// 4-stage smem ring
#define STAGES      4
#define A_PLANE     (BM*SROW*2)            // 18432 B
#define B_PLANE     (BN*SROW*2)            // 9216 B
#define SM_AH       0
#define SM_AL       (A_PLANE)
#define SM_BHI      (2*A_PLANE)
#define SM_BLO      (2*A_PLANE + B_PLANE)
#define STAGE_BYTES (2*A_PLANE + 2*B_PLANE)   // 55296
#define SMEM_DYN    (STAGES*STAGE_BYTES)      // 221184

// ---------------- device scratch (static) ----------------------------------
__device__ __nv_bfloat16 g_hs1h[TSEQ*BH];
__device__ __nv_bfloat16 g_hs1l[TSEQ*BH];
__device__ __nv_bfloat16 g_h1ah[BH], g_h1al[BH], g_h1bh[BH], g_h1bl[BH];
__device__ __nv_bfloat16 g_h2ah[BH], g_h2al[BH], g_h2bh[BH], g_h2bl[BH];
__device__ __nv_bfloat16 g_zbf[BH];
__device__ float g_c1[BH], g_c2[BH];
__device__ float g_decin[BSZ*INDIM];
// split + tile-reordered weights: row = tile*64 + q*16 + hcd, col = k
// 0=eWhh0 1=eWih1 2=eWhh1 3=dWhh0 4=dWih1 5=dWhh1
__device__ __nv_bfloat16 g_wh[6][4*HID*HID];
__device__ __nv_bfloat16 g_wl[6][4*HID*HID];
// combined biases bih+bhh: 0=enc0 1=enc1 2=dec0 3=dec1
__device__ float g_bsum[4][4*HID];

// ---------------- helpers ---------------------------------------------------
__device__ __forceinline__ float fast_sigmoid(float x) {
    return 1.0f / (1.0f + __expf(-x));
}
__device__ __forceinline__ float fast_tanh(float x) {
    return 1.0f - 2.0f / (__expf(2.0f * x) + 1.0f);
}
__device__ __forceinline__ void mma_bf16(float* c, const unsigned* a, const unsigned* b) {
    asm volatile(
        "mma.sync.aligned.m16n8k16.row.col.f32.bf16.bf16.f32 "
        "{%0,%1,%2,%3}, {%4,%5,%6,%7}, {%8,%9}, {%0,%1,%2,%3};\n"
        : "+f"(c[0]), "+f"(c[1]), "+f"(c[2]), "+f"(c[3])
        : "r"(a[0]), "r"(a[1]), "r"(a[2]), "r"(a[3]), "r"(b[0]), "r"(b[1]));
}
__device__ __forceinline__ void ldsm4(unsigned* r, const void* p) {
    unsigned addr = (unsigned)__cvta_generic_to_shared(p);
    asm volatile("ldmatrix.sync.aligned.m8n8.x4.shared.b16 {%0,%1,%2,%3}, [%4];"
        : "=r"(r[0]), "=r"(r[1]), "=r"(r[2]), "=r"(r[3]) : "r"(addr));
}
__device__ __forceinline__ void cp16(void* smem, const void* gmem) {
    unsigned s = (unsigned)__cvta_generic_to_shared(smem);
    asm volatile("cp.async.cg.shared.global [%0], [%1], 16;\n" :: "r"(s), "l"(gmem));
}
__device__ __forceinline__ void cp_commit() {
    asm volatile("cp.async.commit_group;\n");
}
template<int N> __device__ __forceinline__ void cp_wait() {
    asm volatile("cp.async.wait_group %0;\n" :: "n"(N));
}

// Stage one (A 128xBK, W 64xBK) hi/lo tile set into ring buffer `buf`.
__device__ __forceinline__ void stage_tiles(
    char* smem, int buf,
    const __nv_bfloat16* __restrict__ Ah, const __nv_bfloat16* __restrict__ Al,
    const __nv_bfloat16* __restrict__ Wh, const __nv_bfloat16* __restrict__ Wl,
    int b0, int k0)
{
    char* base = smem + buf * STAGE_BYTES;
    const int tid = threadIdx.x;
    #pragma unroll
    for (int i = 0; i < 2; i++) {
        int idx = tid + i * NTHR;        // 0..1023 = 128 rows x 8 chunks of 16B
        int row = idx >> 3, ch = idx & 7;
        int so = (row * SROW + ch * 8) * 2;
        const int go = (b0 + row) * HID + k0 + ch * 8;
        cp16(base + SM_AH + so, Ah + go);
        cp16(base + SM_AL + so, Al + go);
    }
    {
        int idx = tid;                   // 0..511 = 64 rows x 8 chunks
        int row = idx >> 3, ch = idx & 7;
        int so = (row * SROW + ch * 8) * 2;
        const int go = row * HID + k0 + ch * 8;
        cp16(base + SM_BHI + so, Wh + go);
        cp16(base + SM_BLO + so, Wl + go);
    }
    cp_commit();
}

// ---------------- fused LSTM step (mma.sync, 3-pass bf16 split) -------------
// mode 0: input proj via K=2 scalar epilogue (x1 fp32, Wx fp32 [2048,2]); NI=8
// mode 1: input proj via full K=512 GEMM on (A1h/A1l, W1h/W1l); NI=16
__global__ void __launch_bounds__(NTHR)
lstm_step(const __nv_bfloat16* __restrict__ A1h, const __nv_bfloat16* __restrict__ A1l,
          const __nv_bfloat16* __restrict__ W1h, const __nv_bfloat16* __restrict__ W1l,
          const float* __restrict__ x1, int lda1, const float* __restrict__ Wx,
          const __nv_bfloat16* __restrict__ Hinh, const __nv_bfloat16* __restrict__ Hinl,
          const __nv_bfloat16* __restrict__ Whh_h, const __nv_bfloat16* __restrict__ Whh_l,
          const float* __restrict__ bsum,
          __nv_bfloat16* __restrict__ Houth, __nv_bfloat16* __restrict__ Houtl,
          float* __restrict__ C, int mode)
{
    extern __shared__ char smem[];
    const int tid = threadIdx.x;
    const int wid = tid >> 5, lane = tid & 31;
    const int wm = wid >> 2, wn = wid & 3;   // 4x4 warps: 32 rows x 16 cols each
    const int hc0 = blockIdx.x * 16;
    const int b0  = blockIdx.y * BM;
    const int wt  = blockIdx.x * BN * HID;   // weight tile offset
    const int NI  = (mode == 1) ? 16 : 8;

    // ldmatrix lane addressing (byte offsets within a plane)
    const int a_row = (lane & 7) + ((lane >> 3) & 1) * 8;
    const int a_col = (lane >> 4) * 8;
    const int b_row = (lane >> 4) * 8 + (lane & 7);
    const int b_col = ((lane >> 3) & 1) * 8;

    auto srcs = [&](int j, const __nv_bfloat16*& sAh, const __nv_bfloat16*& sAl,
                    const __nv_bfloat16*& sWh, const __nv_bfloat16*& sWl, int& k0) {
        if (mode == 1 && j < 8) {
            sAh = A1h; sAl = A1l; sWh = W1h + wt; sWl = W1l + wt; k0 = j * BK;
        } else {
            int jj = (mode == 1) ? j - 8 : j;
            sAh = Hinh; sAl = Hinl; sWh = Whh_h + wt; sWl = Whh_l + wt; k0 = jj * BK;
        }
    };

    float acc[2][2][4];
    #pragma unroll
    for (int mt = 0; mt < 2; mt++)
        #pragma unroll
        for (int nb = 0; nb < 2; nb++)
            #pragma unroll
            for (int r = 0; r < 4; r++) acc[mt][nb][r] = 0.0f;

    // prologue: fill 3 of the 4 ring slots
    #pragma unroll
    for (int p = 0; p < 3; p++) {
        const __nv_bfloat16 *a, *al, *w, *wl; int k0;
        srcs(p, a, al, w, wl, k0);
        stage_tiles(smem, p, a, al, w, wl, b0, k0);
    }

    #pragma unroll 1
    for (int it = 0; it < NI; it++) {
        // complete cp.async group `it`
        if (NI - it >= 3)       cp_wait<2>();
        else if (NI - it == 2)  cp_wait<1>();
        else                    cp_wait<0>();
        __syncthreads();   // all warps see stage it; all done reading stage it-1
        if (it + 3 < NI) {
            const __nv_bfloat16 *a, *al, *w, *wl; int k0;
            srcs(it + 3, a, al, w, wl, k0);
            stage_tiles(smem, (it + 3) & 3, a, al, w, wl, b0, k0);
        }
        char* base = smem + (it & 3) * STAGE_BYTES;
        #pragma unroll
        for (int kk = 0; kk < 4; kk++) {
            unsigned ah[2][4], al[2][4], bh[4], bl[4];
            #pragma unroll
            for (int mt = 0; mt < 2; mt++) {
                int off = ((wm * 32 + mt * 16 + a_row) * SROW + kk * 16 + a_col) * 2;
                ldsm4(ah[mt], base + SM_AH + off);
                ldsm4(al[mt], base + SM_AL + off);
            }
            {
                int off = ((wn * 16 + b_row) * SROW + kk * 16 + b_col) * 2;
                ldsm4(bh, base + SM_BHI + off);
                ldsm4(bl, base + SM_BLO + off);
            }
            // pass-major: spaces same-accumulator HMMAs by 4 issues
            #pragma unroll
            for (int mt = 0; mt < 2; mt++)
                #pragma unroll
                for (int nb = 0; nb < 2; nb++)
                    mma_bf16(acc[mt][nb], ah[mt], &bh[nb * 2]);
            #pragma unroll
            for (int mt = 0; mt < 2; mt++)
                #pragma unroll
                for (int nb = 0; nb < 2; nb++)
                    mma_bf16(acc[mt][nb], ah[mt], &bl[nb * 2]);
            #pragma unroll
            for (int mt = 0; mt < 2; mt++)
                #pragma unroll
                for (int nb = 0; nb < 2; nb++)
                    mma_bf16(acc[mt][nb], al[mt], &bh[nb * 2]);
        }
    }

    // ---- epilogue: gate transpose through smem, then fused cell update ----
    float (*gm)[BN + 4] = reinterpret_cast<float (*)[BN + 4]>(smem);
    __syncthreads();
    {
        int g = lane >> 2, t = lane & 3;
        #pragma unroll
        for (int mt = 0; mt < 2; mt++)
            #pragma unroll
            for (int nb = 0; nb < 2; nb++) {
                int row = wm * 32 + mt * 16 + g;
                int col = wn * 16 + nb * 8 + t * 2;
                gm[row][col]         = acc[mt][nb][0];
                gm[row][col + 1]     = acc[mt][nb][1];
                gm[row + 8][col]     = acc[mt][nb][2];
                gm[row + 8][col + 1] = acc[mt][nb][3];
            }
    }
    __syncthreads();
    #pragma unroll
    for (int i = 0; i < 4; i++) {
        int idx = tid + i * NTHR;      // 0..2047 over 128 batch x 16 hc
        int hcd = idx & 15, br = idx >> 4;
        int b = b0 + br, hc = hc0 + hcd;
        float gv[4];
        #pragma unroll
        for (int q = 0; q < 4; q++)
            gv[q] = gm[br][q * 16 + hcd] + bsum[q * HID + hc];
        if (mode == 0) {
            float xi0 = x1[b * lda1 + 0];
            float xi1 = x1[b * lda1 + 1];
            #pragma unroll
            for (int q = 0; q < 4; q++) {
                int gg = q * HID + hc;
                gv[q] += xi0 * Wx[gg * INDIM + 0] + xi1 * Wx[gg * INDIM + 1];
            }
        }
        float ig = fast_sigmoid(gv[0]);
        float fg = fast_sigmoid(gv[1]);
        float gg = fast_tanh(gv[2]);
        float og = fast_sigmoid(gv[3]);
        int ci = b * HID + hc;
        float c = C[ci];
        c = fg * c + ig * gg;
        C[ci] = c;
        float h = og * fast_tanh(c);
        __nv_bfloat16 hh = __float2bfloat16(h);
        Houth[ci] = hh;
        Houtl[ci] = __float2bfloat16(h - __bfloat162float(hh));
    }
}

// One fused conversion kernel: 6 weight matrices -> split/tile-reordered planes.
__global__ void convert_all(const float* __restrict__ s0, const float* __restrict__ s1,
                            const float* __restrict__ s2, const float* __restrict__ s3,
                            const float* __restrict__ s4, const float* __restrict__ s5,
                            __nv_bfloat16* __restrict__ dhb,
                            __nv_bfloat16* __restrict__ dlb)
{
    const int WSZ = 4 * HID * HID;
    int m = blockIdx.x >> 12;                    // matrix index 0..5
    int j = ((blockIdx.x & 4095) << 8) + threadIdx.x;   // 0..WSZ-1
    const float* src;
    switch (m) {
        case 0: src = s0; break;
        case 1: src = s1; break;
        case 2: src = s2; break;
        case 3: src = s3; break;
        case 4: src = s4; break;
        default: src = s5; break;
    }
    int g = j >> 9, k = j & 511;
    int q = g >> 9, hc = g & 511;
    int tile = hc >> 4, hcd = hc & 15;
    int dr = m * WSZ + ((tile * 4 + q) * 16 + hcd) * HID + k;
    float w = src[j];
    __nv_bfloat16 h = __float2bfloat16(w);
    dhb[dr] = h;
    dlb[dr] = __float2bfloat16(w - __bfloat162float(h));
}

// Fused init: zero states + combined biases.
__global__ void setup_init(const float* __restrict__ eb0a, const float* __restrict__ eb0b,
                           const float* __restrict__ eb1a, const float* __restrict__ eb1b,
                           const float* __restrict__ db0a, const float* __restrict__ db0b,
                           const float* __restrict__ db1a, const float* __restrict__ db1b)
{
    int i = blockIdx.x * blockDim.x + threadIdx.x;
    if (i < BH) {
        g_zbf[i] = __ushort_as_bfloat16((unsigned short)0);
        g_c1[i] = 0.0f;
        g_c2[i] = 0.0f;
    }
    if (i < BSZ * INDIM) g_decin[i] = 0.0f;
    if (i < 4 * HID) {
        g_bsum[0][i] = eb0a[i] + eb0b[i];
        g_bsum[1][i] = eb1a[i] + eb1b[i];
        g_bsum[2][i] = db0a[i] + db0b[i];
        g_bsum[3][i] = db1a[i] + db1b[i];
    }
}

// pred[b,k] = (hi+lo)(h2[b,:]) . fcW[k,:] + fcb[k]
__global__ void pred_kernel(const __nv_bfloat16* __restrict__ h2h,
                            const __nv_bfloat16* __restrict__ h2l,
                            const float* __restrict__ fcW,
                            const float* __restrict__ fcb,
                            float* __restrict__ out, int s)
{
    int warp = threadIdx.x >> 5;
    int lane = threadIdx.x & 31;
    int b = blockIdx.x * 4 + warp;
    float a0 = 0.0f, a1 = 0.0f;
    #pragma unroll
    for (int j = lane; j < HID; j += 32) {
        float h = __bfloat162float(h2h[b * HID + j]) + __bfloat162float(h2l[b * HID + j]);
        a0 += h * fcW[j];
        a1 += h * fcW[HID + j];
    }
    #pragma unroll
    for (int o = 16; o; o >>= 1) {
        a0 += __shfl_xor_sync(0xffffffffu, a0, o);
        a1 += __shfl_xor_sync(0xffffffffu, a1, o);
    }
    if (lane == 0) {
        float p0 = a0 + fcb[0], p1 = a1 + fcb[1];
        out[b * HOR * 2 + s * 2 + 0] = p0;
        out[b * HOR * 2 + s * 2 + 1] = p1;
        g_decin[b * 2 + 0] = p0;
        g_decin[b * 2 + 1] = p1;
    }
}

extern "C" void kernel_launch(void* const* d_in, const int* in_sizes, int n_in,
                              void* d_out, int out_size)
{
    const float* x      = (const float*)d_in[0];
    const float* eWih0  = (const float*)d_in[1];
    const float* eWhh0  = (const float*)d_in[2];
    const float* ebih0  = (const float*)d_in[3];
    const float* ebhh0  = (const float*)d_in[4];
    const float* eWih1  = (const float*)d_in[5];
    const float* eWhh1  = (const float*)d_in[6];
    const float* ebih1  = (const float*)d_in[7];
    const float* ebhh1  = (const float*)d_in[8];
    const float* dWih0  = (const float*)d_in[9];
    const float* dWhh0  = (const float*)d_in[10];
    const float* dbih0  = (const float*)d_in[11];
    const float* dbhh0  = (const float*)d_in[12];
    const float* dWih1  = (const float*)d_in[13];
    const float* dWhh1  = (const float*)d_in[14];
    const float* dbih1  = (const float*)d_in[15];
    const float* dbhh1  = (const float*)d_in[16];
    const float* fcW    = (const float*)d_in[17];
    const float* fcb    = (const float*)d_in[18];
    float* out = (float*)d_out;

    __nv_bfloat16 *hs1h, *hs1l, *h1ah, *h1al, *h1bh, *h1bl;
    __nv_bfloat16 *h2ah, *h2al, *h2bh, *h2bl, *zb, *whb, *wlb;
    float *c1, *c2, *decin, *bsb;
    cudaGetSymbolAddress((void**)&hs1h, g_hs1h);
    cudaGetSymbolAddress((void**)&hs1l, g_hs1l);
    cudaGetSymbolAddress((void**)&h1ah, g_h1ah);
    cudaGetSymbolAddress((void**)&h1al, g_h1al);
    cudaGetSymbolAddress((void**)&h1bh, g_h1bh);
    cudaGetSymbolAddress((void**)&h1bl, g_h1bl);
    cudaGetSymbolAddress((void**)&h2ah, g_h2ah);
    cudaGetSymbolAddress((void**)&h2al, g_h2al);
    cudaGetSymbolAddress((void**)&h2bh, g_h2bh);
    cudaGetSymbolAddress((void**)&h2bl, g_h2bl);
    cudaGetSymbolAddress((void**)&zb,   g_zbf);
    cudaGetSymbolAddress((void**)&whb,  g_wh);
    cudaGetSymbolAddress((void**)&wlb,  g_wl);
    cudaGetSymbolAddress((void**)&c1,   g_c1);
    cudaGetSymbolAddress((void**)&c2,   g_c2);
    cudaGetSymbolAddress((void**)&decin, g_decin);
    cudaGetSymbolAddress((void**)&bsb,  g_bsum);

    const int WSZ = 4 * HID * HID;
    __nv_bfloat16 *wh_eWhh0 = whb + 0 * WSZ, *wl_eWhh0 = wlb + 0 * WSZ;
    __nv_bfloat16 *wh_eWih1 = whb + 1 * WSZ, *wl_eWih1 = wlb + 1 * WSZ;
    __nv_bfloat16 *wh_eWhh1 = whb + 2 * WSZ, *wl_eWhh1 = wlb + 2 * WSZ;
    __nv_bfloat16 *wh_dWhh0 = whb + 3 * WSZ, *wl_dWhh0 = wlb + 3 * WSZ;
    __nv_bfloat16 *wh_dWih1 = whb + 4 * WSZ, *wl_dWih1 = wlb + 4 * WSZ;
    __nv_bfloat16 *wh_dWhh1 = whb + 5 * WSZ, *wl_dWhh1 = wlb + 5 * WSZ;
    float *bs_e0 = bsb + 0 * 4 * HID, *bs_e1 = bsb + 1 * 4 * HID;
    float *bs_d0 = bsb + 2 * 4 * HID, *bs_d1 = bsb + 3 * 4 * HID;

    cudaFuncSetAttribute(lstm_step, cudaFuncAttributeMaxDynamicSharedMemorySize,
                         SMEM_DYN);

    // 2 setup launches (keeps ncu's -s 5 window on lstm_step)
    setup_init<<<(BH + 255) / 256, 256>>>(ebih0, ebhh0, ebih1, ebhh1,
                                          dbih0, dbhh0, dbih1, dbhh1);
    convert_all<<<6 * 4096, 256>>>(eWhh0, eWih1, eWhh1, dWhh0, dWih1, dWhh1,
                                   whb, wlb);

    dim3 grid(HID / 16, BSZ / BM);   // (32, 4) = 128 CTAs

    // Encoder layer 1 (mode 0). h chain lives in hs1 planes.
    for (int t = 0; t < TSEQ; t++) {
        const __nv_bfloat16* hinh = t ? (hs1h + (size_t)(t - 1) * BH) : zb;
        const __nv_bfloat16* hinl = t ? (hs1l + (size_t)(t - 1) * BH) : zb;
        lstm_step<<<grid, NTHR, SMEM_DYN>>>(
            nullptr, nullptr, nullptr, nullptr,
            x + t * INDIM, TSEQ * INDIM, eWih0,
            hinh, hinl, wh_eWhh0, wl_eWhh0, bs_e0,
            hs1h + (size_t)t * BH, hs1l + (size_t)t * BH, c1, 0);
    }
    // Encoder layer 2 (mode 1): final state ends in h2b (T even)
    for (int t = 0; t < TSEQ; t++) {
        const __nv_bfloat16* hinh = (t == 0) ? zb : ((t & 1) ? h2ah : h2bh);
        const __nv_bfloat16* hinl = (t == 0) ? zb : ((t & 1) ? h2al : h2bl);
        __nv_bfloat16* houth = (t & 1) ? h2bh : h2ah;
        __nv_bfloat16* houtl = (t & 1) ? h2bl : h2al;
        lstm_step<<<grid, NTHR, SMEM_DYN>>>(
            hs1h + (size_t)t * BH, hs1l + (size_t)t * BH, wh_eWih1, wl_eWih1,
            nullptr, 0, nullptr,
            hinh, hinl, wh_eWhh1, wl_eWhh1, bs_e1, houth, houtl, c2, 1);
    }
    // Decoder
    for (int s = 0; s < HOR; s++) {
        const __nv_bfloat16* h1inh = (s == 0) ? (hs1h + (size_t)(TSEQ - 1) * BH)
                                              : ((s & 1) ? h1ah : h1bh);
        const __nv_bfloat16* h1inl = (s == 0) ? (hs1l + (size_t)(TSEQ - 1) * BH)
                                              : ((s & 1) ? h1al : h1bl);
        __nv_bfloat16* h1outh = (s & 1) ? h1bh : h1ah;
        __nv_bfloat16* h1outl = (s & 1) ? h1bl : h1al;
        lstm_step<<<grid, NTHR, SMEM_DYN>>>(
            nullptr, nullptr, nullptr, nullptr,
            decin, INDIM, dWih0,
            h1inh, h1inl, wh_dWhh0, wl_dWhh0, bs_d0, h1outh, h1outl, c1, 0);

        const __nv_bfloat16* h2inh = (s == 0) ? h2bh : ((s & 1) ? h2ah : h2bh);
        const __nv_bfloat16* h2inl = (s == 0) ? h2bl : ((s & 1) ? h2al : h2bl);
        __nv_bfloat16* h2outh = (s & 1) ? h2bh : h2ah;
        __nv_bfloat16* h2outl = (s & 1) ? h2bl : h2al;
        lstm_step<<<grid, NTHR, SMEM_DYN>>>(
            h1outh, h1outl, wh_dWih1, wl_dWih1,
            nullptr, 0, nullptr,
            h2inh, h2inl, wh_dWhh1, wl_dWhh1, bs_d1, h2outh, h2outl, c2, 1);

        pred_kernel<<<BSZ / 4, 128>>>(h2outh, h2outl, fcW, fcb, out, s);
    }
}